// round 9
// baseline (speedup 1.0000x reference)
#include <cuda_runtime.h>
#include <cuda_fp16.h>
#include <math.h>

// Problem constants
#define BB   2
#define TT   2048
#define HH   1024
#define NH   16
#define HD   64
#define MM   (BB*TT)        // 4096
#define NGRP 32
#define GSZ  (HH/NGRP)      // 32
#define GELEM (TT*GSZ)      // 65536

// Scratch (device globals; no allocation allowed)
__device__ __half  g_xn[MM*HH];          // normalized activations (fp16)
__device__ __half  g_q [MM*HH];          // q  [b,h,t,d] fp16
__device__ __half  g_kr[MM*HH];          // k  [b,h,t,d] fp16
__device__ __half  g_vt[MM*HH];          // v^T [b,h,d,t] fp16
__device__ __half  g_a [MM*HH];          // attention out fp16
__device__ float   g_x1[MM*HH];          // residual stream (fp32, exact)
__device__ __half  g_h [MM*4*HH];        // MLP hidden fp16
__device__ __half2 g_wattn [(HH/2)*(3*HH)];   // k-pair-packed fp16 weights
__device__ __half2 g_waproj[(HH/2)*HH];
__device__ __half2 g_wfc   [(HH/2)*(4*HH)];
__device__ __half2 g_wmproj[(4*HH/2)*HH];
__device__ float   g_part[512*2];        // groupnorm partial sums

__device__ __forceinline__ unsigned pk2(float a, float b) {
    __half2 h = __floats2half2_rn(a, b);   // x(lo)=a, y(hi)=b
    return *(unsigned*)&h;
}

// ---------------------------------------------------------------------------
// Pack weights: fp32 [K][N] -> half2 [K/2][N], pair = (w[2k2][n], w[2k2+1][n])
// ---------------------------------------------------------------------------
__global__ void pack_w_kernel(const float* __restrict__ in,
                              __half2* __restrict__ out, int K, int N)
{
    int total = (K / 2) * (N / 4);
    int i = blockIdx.x * blockDim.x + threadIdx.x;
    int stride = gridDim.x * blockDim.x;
    int nq = N / 4;
    for (; i < total; i += stride) {
        int k2 = i / nq;
        int n  = (i - k2 * nq) * 4;
        float4 r0 = *(const float4*)(in + (size_t)(2 * k2) * N + n);
        float4 r1 = *(const float4*)(in + (size_t)(2 * k2 + 1) * N + n);
        uint4 u = make_uint4(pk2(r0.x, r1.x), pk2(r0.y, r1.y),
                             pk2(r0.z, r1.z), pk2(r0.w, r1.w));
        *(uint4*)(out + (size_t)k2 * N + n) = u;
    }
}

// ---------------------------------------------------------------------------
// GroupNorm: stats (512 partial blocks) + apply (fp16 out)
// ---------------------------------------------------------------------------
__global__ void gn_stats_kernel(const float* __restrict__ x,
                                float* __restrict__ part)
{
    int bg = blockIdx.x >> 3;
    int slice = blockIdx.x & 7;
    int batch = bg >> 5, g = bg & 31;
    const float* xp = x + (size_t)batch * TT * HH + g * GSZ;
    int t = slice * 256 + threadIdx.x;
    const float4* row = (const float4*)(xp + (size_t)t * HH);
    float s = 0.f, ss = 0.f;
    #pragma unroll
    for (int i = 0; i < 8; i++) {
        float4 v = row[i];
        s  += v.x + v.y + v.z + v.w;
        ss += v.x*v.x + v.y*v.y + v.z*v.z + v.w*v.w;
    }
    __shared__ float rs[256], rss[256];
    rs[threadIdx.x] = s; rss[threadIdx.x] = ss;
    __syncthreads();
    for (int o = 128; o > 0; o >>= 1) {
        if (threadIdx.x < o) {
            rs[threadIdx.x]  += rs[threadIdx.x + o];
            rss[threadIdx.x] += rss[threadIdx.x + o];
        }
        __syncthreads();
    }
    if (threadIdx.x == 0) {
        part[blockIdx.x * 2]     = rs[0];
        part[blockIdx.x * 2 + 1] = rss[0];
    }
}

__global__ void gn_apply_kernel(const float* __restrict__ x,
                                const float* __restrict__ part,
                                const float* __restrict__ w,
                                const float* __restrict__ b,
                                __half* __restrict__ y)
{
    __shared__ float s_mean[64], s_rstd[64];
    if (threadIdx.x < 64) {
        float s = 0.f, ss = 0.f;
        #pragma unroll
        for (int i = 0; i < 8; i++) {
            s  += part[(threadIdx.x * 8 + i) * 2];
            ss += part[(threadIdx.x * 8 + i) * 2 + 1];
        }
        float mean = s * (1.0f / GELEM);
        float var  = ss * (1.0f / GELEM) - mean * mean;
        s_mean[threadIdx.x] = mean;
        s_rstd[threadIdx.x] = rsqrtf(var + 1e-5f);
    }
    __syncthreads();

    int n4 = MM * HH / 4;
    int i = blockIdx.x * blockDim.x + threadIdx.x;
    int stride = gridDim.x * blockDim.x;
    for (; i < n4; i += stride) {
        int e = i * 4;
        int ch = e & (HH - 1);
        int batch = e >> 21;              // TT*HH = 2^21
        int bg = batch * 32 + (ch >> 5);
        float mean = s_mean[bg], rstd = s_rstd[bg];
        float4 v = ((const float4*)x)[i];
        uint2 o;
        o.x = pk2((v.x - mean) * rstd * w[ch]   + b[ch],
                  (v.y - mean) * rstd * w[ch+1] + b[ch+1]);
        o.y = pk2((v.z - mean) * rstd * w[ch+2] + b[ch+2],
                  (v.w - mean) * rstd * w[ch+3] + b[ch+3]);
        *(uint2*)(y + (size_t)i * 4) = o;
    }
}

// ---------------------------------------------------------------------------
// FP16 tensor-core GEMM (m16n8k16), cp.async 3-stage pipeline.
// BM=BN=128, BK=64, 256 threads, warp tile 64x32.
// A smem [m][k] half, row stride 72; B smem [k/2][n] half2, row stride 136.
// ---------------------------------------------------------------------------
#define GBM 128
#define GBN 128
#define GBK 64
#define APAD 72                         // halfs
#define BPAD 136                        // half2
#define A_BYTES (GBM*APAD*2)            // 18432
#define B_BYTES ((GBK/2)*BPAD*4)        // 17408
#define STG_BYTES (A_BYTES + B_BYTES)   // 35840
#define NSTAGE 3

__device__ __forceinline__ float gelu_f(float v) {
    const float c = 0.7978845608028654f;
    float u = c * (v + 0.044715f * v * v * v);
    return 0.5f * v * (1.0f + tanhf(u));
}

__device__ __forceinline__ void mma_f16(float* d, const unsigned* a, const unsigned* b) {
    asm volatile(
        "mma.sync.aligned.m16n8k16.row.col.f32.f16.f16.f32 "
        "{%0,%1,%2,%3}, {%4,%5,%6,%7}, {%8,%9}, {%0,%1,%2,%3};"
        : "+f"(d[0]), "+f"(d[1]), "+f"(d[2]), "+f"(d[3])
        : "r"(a[0]), "r"(a[1]), "r"(a[2]), "r"(a[3]),
          "r"(b[0]), "r"(b[1]));
}

__device__ __forceinline__ void cp16(void* dst, const void* src) {
    unsigned d = (unsigned)__cvta_generic_to_shared(dst);
    asm volatile("cp.async.cg.shared.global [%0], [%1], 16;" :: "r"(d), "l"(src));
}

template<int MODE>
__global__ void __launch_bounds__(256, 2)
tgemm_kernel(const __half* __restrict__ A, const __half2* __restrict__ Bp,
             const float* __restrict__ bias, const float* __restrict__ res,
             float* __restrict__ Cf, float* __restrict__ C2, float* __restrict__ C3,
             __half* __restrict__ Ch, __half* __restrict__ KR, __half* __restrict__ VT,
             int M, int N, int K)
{
    extern __shared__ char shraw[];

    int tid  = threadIdx.x;
    int wid  = tid >> 5;
    int lane = tid & 31;
    int wm = wid >> 2;
    int wn = wid & 3;
    int lr = lane >> 2;
    int lc = lane & 3;

    int bm = blockIdx.y * GBM, bn = blockIdx.x * GBN;
    const __half* Aptr = A + (size_t)bm * K;
    const __half2* Bptr = Bp + bn;

    float acc[4][4][4];
    #pragma unroll
    for (int i = 0; i < 4; i++)
        #pragma unroll
        for (int j = 0; j < 4; j++)
            #pragma unroll
            for (int e = 0; e < 4; e++) acc[i][j][e] = 0.f;

    int ntiles = K / GBK;

    // loader lambda-ish macro: A 1024 chunks (row=c>>3, ch=c&7), B 1024 (prow=c>>5, ch=c&31)
    #define LOAD_TILE(stg, k0)                                                        \
    {                                                                                 \
        __half*  sA = (__half*)(shraw + (stg) * STG_BYTES);                           \
        __half2* sB = (__half2*)(shraw + (stg) * STG_BYTES + A_BYTES);                \
        _Pragma("unroll")                                                             \
        for (int r = 0; r < 4; r++) {                                                 \
            int c = tid + r * 256;                                                    \
            int row = c >> 3, ch = (c & 7) * 8;                                       \
            cp16(sA + row * APAD + ch, Aptr + (size_t)row * K + (k0) + ch);           \
        }                                                                             \
        _Pragma("unroll")                                                             \
        for (int r = 0; r < 4; r++) {                                                 \
            int c = tid + r * 256;                                                    \
            int prow = c >> 5, ch = (c & 31) * 4;                                     \
            cp16(sB + prow * BPAD + ch, Bptr + (size_t)((k0)/2 + prow) * N + ch);     \
        }                                                                             \
    }

    // prologue: tiles 0,1 into stages 0,1
    LOAD_TILE(0, 0);
    asm volatile("cp.async.commit_group;");
    LOAD_TILE(1, GBK);
    asm volatile("cp.async.commit_group;");

    int stage = 0, lstage = 2;
    for (int it = 0; it < ntiles; it++) {
        if (it + 2 < ntiles) {
            LOAD_TILE(lstage, (it + 2) * GBK);
        }
        asm volatile("cp.async.commit_group;");
        asm volatile("cp.async.wait_group 2;");
        __syncthreads();

        const __half*  As = (const __half*)(shraw + stage * STG_BYTES);
        const __half2* Bs = (const __half2*)(shraw + stage * STG_BYTES + A_BYTES);

        #pragma unroll
        for (int kk = 0; kk < GBK / 16; kk++) {
            int kb = kk * 16;
            unsigned af[4][4], bf[4][2];
            #pragma unroll
            for (int i = 0; i < 4; i++) {
                int m0 = wm * 64 + i * 16 + lr;
                af[i][0] = *(const unsigned*)(As + (size_t)m0 * APAD + kb + 2*lc);
                af[i][1] = *(const unsigned*)(As + (size_t)(m0 + 8) * APAD + kb + 2*lc);
                af[i][2] = *(const unsigned*)(As + (size_t)m0 * APAD + kb + 2*lc + 8);
                af[i][3] = *(const unsigned*)(As + (size_t)(m0 + 8) * APAD + kb + 2*lc + 8);
            }
            #pragma unroll
            for (int j = 0; j < 4; j++) {
                int n0 = wn * 32 + j * 8 + lr;
                bf[j][0] = *(const unsigned*)(Bs + (size_t)(kk * 8 + lc) * BPAD + n0);
                bf[j][1] = *(const unsigned*)(Bs + (size_t)(kk * 8 + lc + 4) * BPAD + n0);
            }
            #pragma unroll
            for (int i = 0; i < 4; i++)
                #pragma unroll
                for (int j = 0; j < 4; j++)
                    mma_f16(acc[i][j], af[i], bf[j]);
        }
        __syncthreads();

        stage = (stage + 1) % NSTAGE;
        lstage = (lstage + 1) % NSTAGE;
    }
    #undef LOAD_TILE

    #pragma unroll
    for (int i = 0; i < 4; i++) {
        int rbase = bm + wm * 64 + i * 16 + lr;
        #pragma unroll
        for (int j = 0; j < 4; j++) {
            int cbase = bn + wn * 32 + j * 8 + 2 * lc;
            #pragma unroll
            for (int e = 0; e < 4; e++) {
                int m = rbase + (e >> 1) * 8;
                int n = cbase + (e & 1);
                float val = acc[i][j][e] + bias[n];
                if (MODE == 0) {
                    int bidx = m >> 11, t = m & 2047;
                    int part = n >> 10;
                    int nn = n & 1023;
                    int h = nn >> 6, d = nn & 63;
                    size_t idx = ((((size_t)bidx * NH + h) * TT) + t) * HD + d;
                    if (part == 0) {
                        Ch[idx] = __float2half_rn(val);
                    } else if (part == 1) {
                        C2[idx] = val;
                        KR[idx] = __float2half_rn(val);
                    } else {
                        C3[idx] = val;
                        size_t vt = (((size_t)bidx * NH + h) * HD + d) * TT + t;
                        VT[vt] = __float2half_rn(val);
                    }
                } else if (MODE == 1) {
                    size_t idx = (size_t)m * N + n;
                    Cf[idx] = val + res[idx];
                } else {
                    Ch[(size_t)m * N + n] = __float2half_rn(gelu_f(val));
                }
            }
        }
    }
}

// ---------------------------------------------------------------------------
// Flash attention, fp16 tensor cores, 2-stage K/V double buffer.
// ---------------------------------------------------------------------------
#define FPH 72                 // halfs per smem row
#define FTILEH (64*FPH)        // 4608 halfs = 9216 B per tile

__global__ void __launch_bounds__(128, 3)
flash_kernel(const __half* __restrict__ Q, const __half* __restrict__ Kr,
             const __half* __restrict__ Vt, __half* __restrict__ Aout)
{
    extern __shared__ char shraw[];
    __half* shh = (__half*)shraw;
    __half* Ps = shh + 4 * FTILEH;

    int qb = blockIdx.x;
    int bh = blockIdx.y;
    int tid = threadIdx.x;
    int w   = tid >> 5;
    int lane = tid & 31;
    int lr = lane >> 2;
    int lc = lane & 3;

    const __half* qbase  = Q  + ((size_t)bh * TT + (size_t)qb * 64 + w * 16) * HD;
    const __half* kbase  = Kr + (size_t)bh * TT * HD;
    const __half* vtbase = Vt + (size_t)bh * HD * TT;

    // Q fragments for 4 k16-steps
    unsigned qf[4][4];
    #pragma unroll
    for (int kk = 0; kk < 4; kk++) {
        int kb = kk * 16;
        qf[kk][0] = *(const unsigned*)(qbase + (size_t)lr * HD + kb + 2*lc);
        qf[kk][1] = *(const unsigned*)(qbase + (size_t)(lr + 8) * HD + kb + 2*lc);
        qf[kk][2] = *(const unsigned*)(qbase + (size_t)lr * HD + kb + 2*lc + 8);
        qf[kk][3] = *(const unsigned*)(qbase + (size_t)(lr + 8) * HD + kb + 2*lc + 8);
    }

    float oacc[8][4];
    #pragma unroll
    for (int nb = 0; nb < 8; nb++)
        #pragma unroll
        for (int e = 0; e < 4; e++) oacc[nb][e] = 0.f;
    float m0 = -1e30f, m1 = -1e30f, l0 = 0.f, l1 = 0.f;

    #define LOAD_KV(stg, kt0)                                                         \
    {                                                                                 \
        __half* Ks = shh + (stg) * 2 * FTILEH;                                        \
        __half* Vs = Ks + FTILEH;                                                     \
        _Pragma("unroll")                                                             \
        for (int i = 0; i < 4; i++) {                                                 \
            int c = tid + i * 128;                                                    \
            int row = c >> 3, ch = (c & 7) * 8;                                       \
            cp16(Ks + row * FPH + ch, kbase + ((size_t)(kt0) * 64 + row) * HD + ch);  \
            cp16(Vs + row * FPH + ch, vtbase + (size_t)row * TT + (kt0) * 64 + ch);   \
        }                                                                             \
    }

    LOAD_KV(0, 0);
    asm volatile("cp.async.commit_group;");

    for (int kt = 0; kt <= qb; kt++) {
        if (kt + 1 <= qb) {
            LOAD_KV((kt + 1) & 1, kt + 1);
        }
        asm volatile("cp.async.commit_group;");
        asm volatile("cp.async.wait_group 1;");
        __syncthreads();

        const __half* Ks = shh + (kt & 1) * 2 * FTILEH;
        const __half* Vs = Ks + FTILEH;

        // S = Q @ K^T
        float sacc[8][4];
        #pragma unroll
        for (int nb = 0; nb < 8; nb++)
            #pragma unroll
            for (int e = 0; e < 4; e++) sacc[nb][e] = 0.f;

        #pragma unroll
        for (int kk = 0; kk < 4; kk++) {
            int kb = kk * 16;
            unsigned bf[8][2];
            #pragma unroll
            for (int nb = 0; nb < 8; nb++) {
                bf[nb][0] = *(const unsigned*)(Ks + (size_t)(nb * 8 + lr) * FPH + kb + 2*lc);
                bf[nb][1] = *(const unsigned*)(Ks + (size_t)(nb * 8 + lr) * FPH + kb + 2*lc + 8);
            }
            #pragma unroll
            for (int nb = 0; nb < 8; nb++)
                mma_f16(sacc[nb], qf[kk], bf[nb]);
        }

        if (kt == qb) {
            int r0 = w * 16 + lr, r1 = r0 + 8;
            #pragma unroll
            for (int nb = 0; nb < 8; nb++) {
                int c0 = nb * 8 + 2 * lc, c1 = c0 + 1;
                if (c0 > r0) sacc[nb][0] = -1e30f;
                if (c1 > r0) sacc[nb][1] = -1e30f;
                if (c0 > r1) sacc[nb][2] = -1e30f;
                if (c1 > r1) sacc[nb][3] = -1e30f;
            }
        }

        float mx0 = -1e30f, mx1 = -1e30f;
        #pragma unroll
        for (int nb = 0; nb < 8; nb++) {
            mx0 = fmaxf(mx0, fmaxf(sacc[nb][0], sacc[nb][1]));
            mx1 = fmaxf(mx1, fmaxf(sacc[nb][2], sacc[nb][3]));
        }
        mx0 = fmaxf(mx0, __shfl_xor_sync(0xffffffffu, mx0, 1));
        mx0 = fmaxf(mx0, __shfl_xor_sync(0xffffffffu, mx0, 2));
        mx1 = fmaxf(mx1, __shfl_xor_sync(0xffffffffu, mx1, 1));
        mx1 = fmaxf(mx1, __shfl_xor_sync(0xffffffffu, mx1, 2));

        float mn0 = fmaxf(m0, mx0), mn1 = fmaxf(m1, mx1);
        float al0 = __expf(m0 - mn0), al1 = __expf(m1 - mn1);
        float sum0 = 0.f, sum1 = 0.f;
        #pragma unroll
        for (int nb = 0; nb < 8; nb++) {
            float p0 = __expf(sacc[nb][0] - mn0);
            float p1 = __expf(sacc[nb][1] - mn0);
            float p2 = __expf(sacc[nb][2] - mn1);
            float p3 = __expf(sacc[nb][3] - mn1);
            sum0 += p0 + p1; sum1 += p2 + p3;
            *(unsigned*)(Ps + (size_t)(w * 16 + lr) * FPH + nb * 8 + 2*lc)     = pk2(p0, p1);
            *(unsigned*)(Ps + (size_t)(w * 16 + lr + 8) * FPH + nb * 8 + 2*lc) = pk2(p2, p3);
        }
        sum0 += __shfl_xor_sync(0xffffffffu, sum0, 1);
        sum0 += __shfl_xor_sync(0xffffffffu, sum0, 2);
        sum1 += __shfl_xor_sync(0xffffffffu, sum1, 1);
        sum1 += __shfl_xor_sync(0xffffffffu, sum1, 2);
        l0 = l0 * al0 + sum0; l1 = l1 * al1 + sum1;
        m0 = mn0; m1 = mn1;
        #pragma unroll
        for (int nb = 0; nb < 8; nb++) {
            oacc[nb][0] *= al0; oacc[nb][1] *= al0;
            oacc[nb][2] *= al1; oacc[nb][3] *= al1;
        }
        __syncwarp();

        // O += P @ V
        #pragma unroll
        for (int kk = 0; kk < 4; kk++) {
            int kb = kk * 16;
            unsigned af[4];
            af[0] = *(const unsigned*)(Ps + (size_t)(w * 16 + lr) * FPH + kb + 2*lc);
            af[1] = *(const unsigned*)(Ps + (size_t)(w * 16 + lr + 8) * FPH + kb + 2*lc);
            af[2] = *(const unsigned*)(Ps + (size_t)(w * 16 + lr) * FPH + kb + 2*lc + 8);
            af[3] = *(const unsigned*)(Ps + (size_t)(w * 16 + lr + 8) * FPH + kb + 2*lc + 8);
            #pragma unroll
            for (int nb = 0; nb < 8; nb++) {
                unsigned bf[2];
                bf[0] = *(const unsigned*)(Vs + (size_t)(nb * 8 + lr) * FPH + kb + 2*lc);
                bf[1] = *(const unsigned*)(Vs + (size_t)(nb * 8 + lr) * FPH + kb + 2*lc + 8);
                mma_f16(oacc[nb], af, bf);
            }
        }
        __syncthreads();
    }
    #undef LOAD_KV

    int batch = bh >> 4, h = bh & 15;
    float inv0 = 1.0f / l0, inv1 = 1.0f / l1;
    int t0 = qb * 64 + w * 16 + lr;
    #pragma unroll
    for (int nb = 0; nb < 8; nb++) {
        int d0 = h * HD + nb * 8 + 2 * lc;
        *(unsigned*)(Aout + ((size_t)batch * TT + t0) * HH + d0)     = pk2(oacc[nb][0] * inv0, oacc[nb][1] * inv0);
        *(unsigned*)(Aout + ((size_t)batch * TT + t0 + 8) * HH + d0) = pk2(oacc[nb][2] * inv1, oacc[nb][3] * inv1);
    }
}

// ---------------------------------------------------------------------------
// Launch
// ---------------------------------------------------------------------------
extern "C" void kernel_launch(void* const* d_in, const int* in_sizes, int n_in,
                              void* d_out, int out_size)
{
    const float* x       = (const float*)d_in[0];
    const float* w_attn  = (const float*)d_in[1];
    const float* b_attn  = (const float*)d_in[2];
    const float* w_aproj = (const float*)d_in[3];
    const float* b_aproj = (const float*)d_in[4];
    const float* ln1_w   = (const float*)d_in[5];
    const float* ln1_b   = (const float*)d_in[6];
    const float* ln2_w   = (const float*)d_in[7];
    const float* ln2_b   = (const float*)d_in[8];
    const float* w_fc    = (const float*)d_in[9];
    const float* b_fc    = (const float*)d_in[10];
    const float* w_mproj = (const float*)d_in[11];
    const float* b_mproj = (const float*)d_in[12];

    float* out_x = (float*)d_out;
    float* pk = out_x + (size_t)MM * HH;
    float* pv = pk + (size_t)MM * HH;

    __half *xn, *q, *kr, *vt, *a, *h;
    float *x1, *part;
    __half2 *wattn, *waproj, *wfc, *wmproj;
    cudaGetSymbolAddress((void**)&xn, g_xn);
    cudaGetSymbolAddress((void**)&q,  g_q);
    cudaGetSymbolAddress((void**)&kr, g_kr);
    cudaGetSymbolAddress((void**)&vt, g_vt);
    cudaGetSymbolAddress((void**)&a,  g_a);
    cudaGetSymbolAddress((void**)&x1, g_x1);
    cudaGetSymbolAddress((void**)&h,  g_h);
    cudaGetSymbolAddress((void**)&part, g_part);
    cudaGetSymbolAddress((void**)&wattn,  g_wattn);
    cudaGetSymbolAddress((void**)&waproj, g_waproj);
    cudaGetSymbolAddress((void**)&wfc,    g_wfc);
    cudaGetSymbolAddress((void**)&wmproj, g_wmproj);

    size_t gsmem = NSTAGE * STG_BYTES;   // 107520 B
    cudaFuncSetAttribute(tgemm_kernel<0>, cudaFuncAttributeMaxDynamicSharedMemorySize, (int)gsmem);
    cudaFuncSetAttribute(tgemm_kernel<1>, cudaFuncAttributeMaxDynamicSharedMemorySize, (int)gsmem);
    cudaFuncSetAttribute(tgemm_kernel<2>, cudaFuncAttributeMaxDynamicSharedMemorySize, (int)gsmem);
    size_t fsmem = 5 * FTILEH * 2;       // 46080 B
    cudaFuncSetAttribute(flash_kernel, cudaFuncAttributeMaxDynamicSharedMemorySize, (int)fsmem);

    pack_w_kernel<<<1024, 256>>>(w_attn,  wattn,  HH, 3 * HH);
    pack_w_kernel<<<1024, 256>>>(w_aproj, waproj, HH, HH);
    pack_w_kernel<<<1024, 256>>>(w_fc,    wfc,    HH, 4 * HH);
    pack_w_kernel<<<1024, 256>>>(w_mproj, wmproj, 4 * HH, HH);

    gn_stats_kernel<<<512, 256>>>(x, part);
    gn_apply_kernel<<<1024, 256>>>(x, part, ln1_w, ln1_b, xn);

    tgemm_kernel<0><<<dim3(3 * HH / GBN, MM / GBM), 256, gsmem>>>(
        xn, wattn, b_attn, nullptr, nullptr, pk, pv, q, kr, vt, MM, 3 * HH, HH);

    flash_kernel<<<dim3(TT / 64, BB * NH), 128, fsmem>>>(q, kr, vt, a);

    tgemm_kernel<1><<<dim3(HH / GBN, MM / GBM), 256, gsmem>>>(
        a, waproj, b_aproj, x, x1, nullptr, nullptr, nullptr, nullptr, nullptr, MM, HH, HH);

    gn_stats_kernel<<<512, 256>>>(x1, part);
    gn_apply_kernel<<<1024, 256>>>(x1, part, ln2_w, ln2_b, xn);

    tgemm_kernel<2><<<dim3(4 * HH / GBN, MM / GBM), 256, gsmem>>>(
        xn, wfc, b_fc, nullptr, nullptr, nullptr, nullptr, h, nullptr, nullptr, MM, 4 * HH, HH);

    tgemm_kernel<1><<<dim3(HH / GBN, MM / GBM), 256, gsmem>>>(
        h, wmproj, b_mproj, x1, out_x, nullptr, nullptr, nullptr, nullptr, nullptr, MM, HH, 4 * HH);
}

// round 11
// speedup vs baseline: 1.0073x; 1.0073x over previous
#include <cuda_runtime.h>
#include <cuda_fp16.h>
#include <math.h>

// Problem constants
#define BB   2
#define TT   2048
#define HH   1024
#define NH   16
#define HD   64
#define MM   (BB*TT)        // 4096
#define GELEM (TT*32)

// Scratch (device globals; no allocation allowed)
__device__ __half  g_xn[MM*HH];
__device__ __half  g_q [MM*HH];          // q  [b,h,t,d] fp16
__device__ __half  g_kr[MM*HH];          // k  [b,h,t,d] fp16
__device__ __half  g_vt[MM*HH];          // v^T [b,h,d,t] fp16
__device__ __half  g_a [MM*HH];
__device__ float   g_x1[MM*HH];
__device__ __half  g_h [MM*4*HH];
__device__ __half2 g_wattn [(HH/2)*(3*HH)];
__device__ __half2 g_waproj[(HH/2)*HH];
__device__ __half2 g_wfc   [(HH/2)*(4*HH)];
__device__ __half2 g_wmproj[(4*HH/2)*HH];
__device__ float   g_part[512*2];

__device__ __forceinline__ unsigned pk2(float a, float b) {
    __half2 h = __floats2half2_rn(a, b);
    return *(unsigned*)&h;
}

// ---------------------------------------------------------------------------
// Pack weights: fp32 [K][N] -> half2 [K/2][N]
// ---------------------------------------------------------------------------
__global__ void pack_w_kernel(const float* __restrict__ in,
                              __half2* __restrict__ out, int K, int N)
{
    int total = (K / 2) * (N / 4);
    int i = blockIdx.x * blockDim.x + threadIdx.x;
    int stride = gridDim.x * blockDim.x;
    int nq = N / 4;
    for (; i < total; i += stride) {
        int k2 = i / nq;
        int n  = (i - k2 * nq) * 4;
        float4 r0 = *(const float4*)(in + (size_t)(2 * k2) * N + n);
        float4 r1 = *(const float4*)(in + (size_t)(2 * k2 + 1) * N + n);
        uint4 u = make_uint4(pk2(r0.x, r1.x), pk2(r0.y, r1.y),
                             pk2(r0.z, r1.z), pk2(r0.w, r1.w));
        *(uint4*)(out + (size_t)k2 * N + n) = u;
    }
}

// ---------------------------------------------------------------------------
// GroupNorm: stats + apply
// ---------------------------------------------------------------------------
__global__ void gn_stats_kernel(const float* __restrict__ x,
                                float* __restrict__ part)
{
    int bg = blockIdx.x >> 3;
    int slice = blockIdx.x & 7;
    int batch = bg >> 5, g = bg & 31;
    const float* xp = x + (size_t)batch * TT * HH + g * 32;
    int t = slice * 256 + threadIdx.x;
    const float4* row = (const float4*)(xp + (size_t)t * HH);
    float s = 0.f, ss = 0.f;
    #pragma unroll
    for (int i = 0; i < 8; i++) {
        float4 v = row[i];
        s  += v.x + v.y + v.z + v.w;
        ss += v.x*v.x + v.y*v.y + v.z*v.z + v.w*v.w;
    }
    __shared__ float rs[256], rss[256];
    rs[threadIdx.x] = s; rss[threadIdx.x] = ss;
    __syncthreads();
    for (int o = 128; o > 0; o >>= 1) {
        if (threadIdx.x < o) {
            rs[threadIdx.x]  += rs[threadIdx.x + o];
            rss[threadIdx.x] += rss[threadIdx.x + o];
        }
        __syncthreads();
    }
    if (threadIdx.x == 0) {
        part[blockIdx.x * 2]     = rs[0];
        part[blockIdx.x * 2 + 1] = rss[0];
    }
}

__global__ void gn_apply_kernel(const float* __restrict__ x,
                                const float* __restrict__ part,
                                const float* __restrict__ w,
                                const float* __restrict__ b,
                                __half* __restrict__ y)
{
    __shared__ float s_mean[64], s_rstd[64];
    if (threadIdx.x < 64) {
        float s = 0.f, ss = 0.f;
        #pragma unroll
        for (int i = 0; i < 8; i++) {
            s  += part[(threadIdx.x * 8 + i) * 2];
            ss += part[(threadIdx.x * 8 + i) * 2 + 1];
        }
        float mean = s * (1.0f / GELEM);
        float var  = ss * (1.0f / GELEM) - mean * mean;
        s_mean[threadIdx.x] = mean;
        s_rstd[threadIdx.x] = rsqrtf(var + 1e-5f);
    }
    __syncthreads();

    int n4 = MM * HH / 4;
    int i = blockIdx.x * blockDim.x + threadIdx.x;
    int stride = gridDim.x * blockDim.x;
    for (; i < n4; i += stride) {
        int e = i * 4;
        int ch = e & (HH - 1);
        int batch = e >> 21;
        int bg = batch * 32 + (ch >> 5);
        float mean = s_mean[bg], rstd = s_rstd[bg];
        float4 v = ((const float4*)x)[i];
        uint2 o;
        o.x = pk2((v.x - mean) * rstd * w[ch]   + b[ch],
                  (v.y - mean) * rstd * w[ch+1] + b[ch+1]);
        o.y = pk2((v.z - mean) * rstd * w[ch+2] + b[ch+2],
                  (v.w - mean) * rstd * w[ch+3] + b[ch+3]);
        *(uint2*)(y + (size_t)i * 4) = o;
    }
}

// ---------------------------------------------------------------------------
// FP16 tensor-core GEMM (m16n8k16), cp.async 3-stage pipeline.
// BM=BN=128, BK=64, 128 threads (4 warps), warp tile 64x64.
// A smem [m][k] half stride 72; B smem [k/2][n] half2 stride 136.
// ---------------------------------------------------------------------------
#define GBM 128
#define GBN 128
#define GBK 64
#define APAD 72
#define BPAD 136
#define A_BYTES (GBM*APAD*2)            // 18432
#define B_BYTES ((GBK/2)*BPAD*4)        // 17408
#define STG_BYTES (A_BYTES + B_BYTES)   // 35840
#define NSTAGE 3

__device__ __forceinline__ float gelu_f(float v) {
    const float c = 0.7978845608028654f;
    float u = c * (v + 0.044715f * v * v * v);
    return 0.5f * v * (1.0f + tanhf(u));
}

__device__ __forceinline__ void mma_f16(float* d, const unsigned* a, const unsigned* b) {
    asm volatile(
        "mma.sync.aligned.m16n8k16.row.col.f32.f16.f16.f32 "
        "{%0,%1,%2,%3}, {%4,%5,%6,%7}, {%8,%9}, {%0,%1,%2,%3};"
        : "+f"(d[0]), "+f"(d[1]), "+f"(d[2]), "+f"(d[3])
        : "r"(a[0]), "r"(a[1]), "r"(a[2]), "r"(a[3]),
          "r"(b[0]), "r"(b[1]));
}

__device__ __forceinline__ void cp16(void* dst, const void* src) {
    unsigned d = (unsigned)__cvta_generic_to_shared(dst);
    asm volatile("cp.async.cg.shared.global [%0], [%1], 16;" :: "r"(d), "l"(src));
}

template<int MODE>
__global__ void __launch_bounds__(128, 2)
tgemm_kernel(const __half* __restrict__ A, const __half2* __restrict__ Bp,
             const float* __restrict__ bias, const float* __restrict__ res,
             float* __restrict__ Cf, float* __restrict__ C2, float* __restrict__ C3,
             __half* __restrict__ Ch, __half* __restrict__ KR, __half* __restrict__ VT,
             int M, int N, int K)
{
    extern __shared__ char shraw[];

    int tid  = threadIdx.x;
    int wid  = tid >> 5;
    int lane = tid & 31;
    int wm = wid >> 1;          // 0..1
    int wn = wid & 1;           // 0..1
    int lr = lane >> 2;         // 0..7
    int lc = lane & 3;          // 0..3

    int bm = blockIdx.y * GBM, bn = blockIdx.x * GBN;
    const __half* Aptr = A + (size_t)bm * K;
    const __half2* Bptr = Bp + bn;

    float acc[4][8][4];
    #pragma unroll
    for (int i = 0; i < 4; i++)
        #pragma unroll
        for (int j = 0; j < 8; j++)
            #pragma unroll
            for (int e = 0; e < 4; e++) acc[i][j][e] = 0.f;

    int ntiles = K / GBK;

    // 128 threads: A 1024 chunks (8 iters), B 1024 chunks (8 iters)
    #define LOAD_TILE(stg, k0)                                                        \
    {                                                                                 \
        __half*  sA = (__half*)(shraw + (stg) * STG_BYTES);                           \
        __half2* sB = (__half2*)(shraw + (stg) * STG_BYTES + A_BYTES);                \
        _Pragma("unroll")                                                             \
        for (int r = 0; r < 8; r++) {                                                 \
            int c = tid + r * 128;                                                    \
            int row = c >> 3, ch = (c & 7) * 8;                                       \
            cp16(sA + row * APAD + ch, Aptr + (size_t)row * K + (k0) + ch);           \
        }                                                                             \
        _Pragma("unroll")                                                             \
        for (int r = 0; r < 8; r++) {                                                 \
            int c = tid + r * 128;                                                    \
            int prow = c >> 5, ch = (c & 31) * 4;                                     \
            cp16(sB + prow * BPAD + ch, Bptr + (size_t)((k0)/2 + prow) * N + ch);     \
        }                                                                             \
    }

    LOAD_TILE(0, 0);
    asm volatile("cp.async.commit_group;");
    LOAD_TILE(1, GBK);
    asm volatile("cp.async.commit_group;");

    int stage = 0, lstage = 2;
    for (int it = 0; it < ntiles; it++) {
        if (it + 2 < ntiles) {
            LOAD_TILE(lstage, (it + 2) * GBK);
        }
        asm volatile("cp.async.commit_group;");
        asm volatile("cp.async.wait_group 2;");
        __syncthreads();

        const __half*  As = (const __half*)(shraw + stage * STG_BYTES);
        const __half2* Bs = (const __half2*)(shraw + stage * STG_BYTES + A_BYTES);

        #pragma unroll
        for (int kk = 0; kk < GBK / 16; kk++) {
            int kb = kk * 16;
            unsigned af[4][4], bf[8][2];
            #pragma unroll
            for (int i = 0; i < 4; i++) {
                int m0 = wm * 64 + i * 16 + lr;
                af[i][0] = *(const unsigned*)(As + (size_t)m0 * APAD + kb + 2*lc);
                af[i][1] = *(const unsigned*)(As + (size_t)(m0 + 8) * APAD + kb + 2*lc);
                af[i][2] = *(const unsigned*)(As + (size_t)m0 * APAD + kb + 2*lc + 8);
                af[i][3] = *(const unsigned*)(As + (size_t)(m0 + 8) * APAD + kb + 2*lc + 8);
            }
            #pragma unroll
            for (int j = 0; j < 8; j++) {
                int n0 = wn * 64 + j * 8 + lr;
                bf[j][0] = *(const unsigned*)(Bs + (size_t)(kk * 8 + lc) * BPAD + n0);
                bf[j][1] = *(const unsigned*)(Bs + (size_t)(kk * 8 + lc + 4) * BPAD + n0);
            }
            #pragma unroll
            for (int i = 0; i < 4; i++)
                #pragma unroll
                for (int j = 0; j < 8; j++)
                    mma_f16(acc[i][j], af[i], bf[j]);
        }
        __syncthreads();

        stage = (stage + 1) % NSTAGE;
        lstage = (lstage + 1) % NSTAGE;
    }
    #undef LOAD_TILE

    #pragma unroll
    for (int i = 0; i < 4; i++) {
        int rbase = bm + wm * 64 + i * 16 + lr;
        #pragma unroll
        for (int j = 0; j < 8; j++) {
            int cbase = bn + wn * 64 + j * 8 + 2 * lc;
            #pragma unroll
            for (int e = 0; e < 4; e++) {
                int m = rbase + (e >> 1) * 8;
                int n = cbase + (e & 1);
                float val = acc[i][j][e] + bias[n];
                if (MODE == 0) {
                    int bidx = m >> 11, t = m & 2047;
                    int part = n >> 10;
                    int nn = n & 1023;
                    int h = nn >> 6, d = nn & 63;
                    size_t idx = ((((size_t)bidx * NH + h) * TT) + t) * HD + d;
                    if (part == 0) {
                        Ch[idx] = __float2half_rn(val);
                    } else if (part == 1) {
                        C2[idx] = val;
                        KR[idx] = __float2half_rn(val);
                    } else {
                        C3[idx] = val;
                        size_t vt = (((size_t)bidx * NH + h) * HD + d) * TT + t;
                        VT[vt] = __float2half_rn(val);
                    }
                } else if (MODE == 1) {
                    size_t idx = (size_t)m * N + n;
                    Cf[idx] = val + res[idx];
                } else {
                    Ch[(size_t)m * N + n] = __float2half_rn(gelu_f(val));
                }
            }
        }
    }
}

// ---------------------------------------------------------------------------
// Flash attention, fp16 tensor cores, 2-stage K/V double buffer (R8 proven).
// ---------------------------------------------------------------------------
#define FPH 72
#define FTILEH (64*FPH)

__global__ void __launch_bounds__(128, 3)
flash_kernel(const __half* __restrict__ Q, const __half* __restrict__ Kr,
             const __half* __restrict__ Vt, __half* __restrict__ Aout)
{
    extern __shared__ char shraw[];
    __half* shh = (__half*)shraw;
    __half* Ps = shh + 4 * FTILEH;

    int qb = blockIdx.x;
    int bh = blockIdx.y;
    int tid = threadIdx.x;
    int w   = tid >> 5;
    int lane = tid & 31;
    int lr = lane >> 2;
    int lc = lane & 3;

    const __half* qbase  = Q  + ((size_t)bh * TT + (size_t)qb * 64 + w * 16) * HD;
    const __half* kbase  = Kr + (size_t)bh * TT * HD;
    const __half* vtbase = Vt + (size_t)bh * HD * TT;

    unsigned qf[4][4];
    #pragma unroll
    for (int kk = 0; kk < 4; kk++) {
        int kb = kk * 16;
        qf[kk][0] = *(const unsigned*)(qbase + (size_t)lr * HD + kb + 2*lc);
        qf[kk][1] = *(const unsigned*)(qbase + (size_t)(lr + 8) * HD + kb + 2*lc);
        qf[kk][2] = *(const unsigned*)(qbase + (size_t)lr * HD + kb + 2*lc + 8);
        qf[kk][3] = *(const unsigned*)(qbase + (size_t)(lr + 8) * HD + kb + 2*lc + 8);
    }

    float oacc[8][4];
    #pragma unroll
    for (int nb = 0; nb < 8; nb++)
        #pragma unroll
        for (int e = 0; e < 4; e++) oacc[nb][e] = 0.f;
    float m0 = -1e30f, m1 = -1e30f, l0 = 0.f, l1 = 0.f;

    #define LOAD_KV(stg, kt0)                                                         \
    {                                                                                 \
        __half* Ks = shh + (stg) * 2 * FTILEH;                                        \
        __half* Vs = Ks + FTILEH;                                                     \
        _Pragma("unroll")                                                             \
        for (int i = 0; i < 4; i++) {                                                 \
            int c = tid + i * 128;                                                    \
            int row = c >> 3, ch = (c & 7) * 8;                                       \
            cp16(Ks + row * FPH + ch, kbase + ((size_t)(kt0) * 64 + row) * HD + ch);  \
            cp16(Vs + row * FPH + ch, vtbase + (size_t)row * TT + (kt0) * 64 + ch);   \
        }                                                                             \
    }

    LOAD_KV(0, 0);
    asm volatile("cp.async.commit_group;");

    for (int kt = 0; kt <= qb; kt++) {
        if (kt + 1 <= qb) {
            LOAD_KV((kt + 1) & 1, kt + 1);
        }
        asm volatile("cp.async.commit_group;");
        asm volatile("cp.async.wait_group 1;");
        __syncthreads();

        const __half* Ks = shh + (kt & 1) * 2 * FTILEH;
        const __half* Vs = Ks + FTILEH;

        float sacc[8][4];
        #pragma unroll
        for (int nb = 0; nb < 8; nb++)
            #pragma unroll
            for (int e = 0; e < 4; e++) sacc[nb][e] = 0.f;

        #pragma unroll
        for (int kk = 0; kk < 4; kk++) {
            int kb = kk * 16;
            #pragma unroll
            for (int nb = 0; nb < 8; nb++) {
                unsigned bf[2];
                bf[0] = *(const unsigned*)(Ks + (size_t)(nb * 8 + lr) * FPH + kb + 2*lc);
                bf[1] = *(const unsigned*)(Ks + (size_t)(nb * 8 + lr) * FPH + kb + 2*lc + 8);
                mma_f16(sacc[nb], qf[kk], bf);
            }
        }

        if (kt == qb) {
            int r0 = w * 16 + lr, r1 = r0 + 8;
            #pragma unroll
            for (int nb = 0; nb < 8; nb++) {
                int c0 = nb * 8 + 2 * lc, c1 = c0 + 1;
                if (c0 > r0) sacc[nb][0] = -1e30f;
                if (c1 > r0) sacc[nb][1] = -1e30f;
                if (c0 > r1) sacc[nb][2] = -1e30f;
                if (c1 > r1) sacc[nb][3] = -1e30f;
            }
        }

        float mx0 = -1e30f, mx1 = -1e30f;
        #pragma unroll
        for (int nb = 0; nb < 8; nb++) {
            mx0 = fmaxf(mx0, fmaxf(sacc[nb][0], sacc[nb][1]));
            mx1 = fmaxf(mx1, fmaxf(sacc[nb][2], sacc[nb][3]));
        }
        mx0 = fmaxf(mx0, __shfl_xor_sync(~0u, mx0, 1));
        mx0 = fmaxf(mx0, __shfl_xor_sync(~0u, mx0, 2));
        mx1 = fmaxf(mx1, __shfl_xor_sync(~0u, mx1, 1));
        mx1 = fmaxf(mx1, __shfl_xor_sync(~0u, mx1, 2));

        float mn0 = fmaxf(m0, mx0), mn1 = fmaxf(m1, mx1);
        float al0 = __expf(m0 - mn0), al1 = __expf(m1 - mn1);
        float sum0 = 0.f, sum1 = 0.f;
        #pragma unroll
        for (int nb = 0; nb < 8; nb++) {
            float p0 = __expf(sacc[nb][0] - mn0);
            float p1 = __expf(sacc[nb][1] - mn0);
            float p2 = __expf(sacc[nb][2] - mn1);
            float p3 = __expf(sacc[nb][3] - mn1);
            sum0 += p0 + p1; sum1 += p2 + p3;
            *(unsigned*)(Ps + (size_t)(w * 16 + lr) * FPH + nb * 8 + 2*lc)     = pk2(p0, p1);
            *(unsigned*)(Ps + (size_t)(w * 16 + lr + 8) * FPH + nb * 8 + 2*lc) = pk2(p2, p3);
        }
        sum0 += __shfl_xor_sync(~0u, sum0, 1);
        sum0 += __shfl_xor_sync(~0u, sum0, 2);
        sum1 += __shfl_xor_sync(~0u, sum1, 1);
        sum1 += __shfl_xor_sync(~0u, sum1, 2);
        l0 = l0 * al0 + sum0; l1 = l1 * al1 + sum1;
        m0 = mn0; m1 = mn1;
        #pragma unroll
        for (int nb = 0; nb < 8; nb++) {
            oacc[nb][0] *= al0; oacc[nb][1] *= al0;
            oacc[nb][2] *= al1; oacc[nb][3] *= al1;
        }
        __syncwarp();

        #pragma unroll
        for (int kk = 0; kk < 4; kk++) {
            int kb = kk * 16;
            unsigned af[4];
            af[0] = *(const unsigned*)(Ps + (size_t)(w * 16 + lr) * FPH + kb + 2*lc);
            af[1] = *(const unsigned*)(Ps + (size_t)(w * 16 + lr + 8) * FPH + kb + 2*lc);
            af[2] = *(const unsigned*)(Ps + (size_t)(w * 16 + lr) * FPH + kb + 2*lc + 8);
            af[3] = *(const unsigned*)(Ps + (size_t)(w * 16 + lr + 8) * FPH + kb + 2*lc + 8);
            #pragma unroll
            for (int nb = 0; nb < 8; nb++) {
                unsigned bf[2];
                bf[0] = *(const unsigned*)(Vs + (size_t)(nb * 8 + lr) * FPH + kb + 2*lc);
                bf[1] = *(const unsigned*)(Vs + (size_t)(nb * 8 + lr) * FPH + kb + 2*lc + 8);
                mma_f16(oacc[nb], af, bf);
            }
        }
        __syncthreads();
    }
    #undef LOAD_KV

    int batch = bh >> 4, h = bh & 15;
    float inv0 = 1.0f / l0, inv1 = 1.0f / l1;
    int t0 = qb * 64 + w * 16 + lr;
    #pragma unroll
    for (int nb = 0; nb < 8; nb++) {
        int d0 = h * HD + nb * 8 + 2 * lc;
        *(unsigned*)(Aout + ((size_t)batch * TT + t0) * HH + d0)     = pk2(oacc[nb][0] * inv0, oacc[nb][1] * inv0);
        *(unsigned*)(Aout + ((size_t)batch * TT + t0 + 8) * HH + d0) = pk2(oacc[nb][2] * inv1, oacc[nb][3] * inv1);
    }
}

// ---------------------------------------------------------------------------
// Launch
// ---------------------------------------------------------------------------
extern "C" void kernel_launch(void* const* d_in, const int* in_sizes, int n_in,
                              void* d_out, int out_size)
{
    const float* x       = (const float*)d_in[0];
    const float* w_attn  = (const float*)d_in[1];
    const float* b_attn  = (const float*)d_in[2];
    const float* w_aproj = (const float*)d_in[3];
    const float* b_aproj = (const float*)d_in[4];
    const float* ln1_w   = (const float*)d_in[5];
    const float* ln1_b   = (const float*)d_in[6];
    const float* ln2_w   = (const float*)d_in[7];
    const float* ln2_b   = (const float*)d_in[8];
    const float* w_fc    = (const float*)d_in[9];
    const float* b_fc    = (const float*)d_in[10];
    const float* w_mproj = (const float*)d_in[11];
    const float* b_mproj = (const float*)d_in[12];

    float* out_x = (float*)d_out;
    float* pk = out_x + (size_t)MM * HH;
    float* pv = pk + (size_t)MM * HH;

    __half *xn, *q, *kr, *vt, *a, *h;
    float *x1, *part;
    __half2 *wattn, *waproj, *wfc, *wmproj;
    cudaGetSymbolAddress((void**)&xn, g_xn);
    cudaGetSymbolAddress((void**)&q,  g_q);
    cudaGetSymbolAddress((void**)&kr, g_kr);
    cudaGetSymbolAddress((void**)&vt, g_vt);
    cudaGetSymbolAddress((void**)&a,  g_a);
    cudaGetSymbolAddress((void**)&x1, g_x1);
    cudaGetSymbolAddress((void**)&h,  g_h);
    cudaGetSymbolAddress((void**)&part, g_part);
    cudaGetSymbolAddress((void**)&wattn,  g_wattn);
    cudaGetSymbolAddress((void**)&waproj, g_waproj);
    cudaGetSymbolAddress((void**)&wfc,    g_wfc);
    cudaGetSymbolAddress((void**)&wmproj, g_wmproj);

    size_t gsmem = NSTAGE * STG_BYTES;   // 107520 B
    cudaFuncSetAttribute(tgemm_kernel<0>, cudaFuncAttributeMaxDynamicSharedMemorySize, (int)gsmem);
    cudaFuncSetAttribute(tgemm_kernel<1>, cudaFuncAttributeMaxDynamicSharedMemorySize, (int)gsmem);
    cudaFuncSetAttribute(tgemm_kernel<2>, cudaFuncAttributeMaxDynamicSharedMemorySize, (int)gsmem);
    size_t fsmem = 5 * FTILEH * 2;       // 46080 B
    cudaFuncSetAttribute(flash_kernel, cudaFuncAttributeMaxDynamicSharedMemorySize, (int)fsmem);

    pack_w_kernel<<<1024, 256>>>(w_attn,  wattn,  HH, 3 * HH);
    pack_w_kernel<<<1024, 256>>>(w_aproj, waproj, HH, HH);
    pack_w_kernel<<<1024, 256>>>(w_fc,    wfc,    HH, 4 * HH);
    pack_w_kernel<<<1024, 256>>>(w_mproj, wmproj, 4 * HH, HH);

    gn_stats_kernel<<<512, 256>>>(x, part);
    gn_apply_kernel<<<1024, 256>>>(x, part, ln1_w, ln1_b, xn);

    tgemm_kernel<0><<<dim3(3 * HH / GBN, MM / GBM), 128, gsmem>>>(
        xn, wattn, b_attn, nullptr, nullptr, pk, pv, q, kr, vt, MM, 3 * HH, HH);

    flash_kernel<<<dim3(TT / 64, BB * NH), 128, fsmem>>>(q, kr, vt, a);

    tgemm_kernel<1><<<dim3(HH / GBN, MM / GBM), 128, gsmem>>>(
        a, waproj, b_aproj, x, x1, nullptr, nullptr, nullptr, nullptr, nullptr, MM, HH, HH);

    gn_stats_kernel<<<512, 256>>>(x1, part);
    gn_apply_kernel<<<1024, 256>>>(x1, part, ln2_w, ln2_b, xn);

    tgemm_kernel<2><<<dim3(4 * HH / GBN, MM / GBM), 128, gsmem>>>(
        xn, wfc, b_fc, nullptr, nullptr, nullptr, nullptr, h, nullptr, nullptr, MM, 4 * HH, HH);

    tgemm_kernel<1><<<dim3(HH / GBN, MM / GBM), 128, gsmem>>>(
        h, wmproj, b_mproj, x1, out_x, nullptr, nullptr, nullptr, nullptr, nullptr, MM, HH, 4 * HH);
}